// round 5
// baseline (speedup 1.0000x reference)
#include <cuda_runtime.h>
#include <cuda_bf16.h>
#include <cstdint>
#include <cstddef>

#define BATCH 128
#define SEQ   512
#define IND   768
#define HID   64
#define NKC   (IND / 16)       // 48 k-chunks
#define NFRAG (NKC * 8 * 32)   // fragment count * lanes

// Scratch (allocation-free rule: __device__ globals). +HID pad: the recurrence
// prefetches pre[t+1] unconditionally, including t=511 of the last batch.
__device__ float    g_pre0[BATCH * SEQ * HID + HID];
__device__ uint32_t g_WfragHi[NFRAG * 2];        // W_ih0 hi bf16, mma-B packed
__device__ uint32_t g_WfragLo[NFRAG * 2];        // W_ih0 lo bf16, mma-B packed

// ---------------------------------------------------------------------------
// Kernel 0: split W_ih0 into bf16 hi/lo AND pack into mma B-fragment layout.
// ---------------------------------------------------------------------------
__global__ void split_w_kernel(const float* __restrict__ W) {
    int idx = blockIdx.x * 256 + threadIdx.x;       // 0 .. NFRAG*2-1
    if (idx >= NFRAG * 2) return;
    int r    = idx & 1;
    int lane = (idx >> 1) & 31;
    int nt   = (idx >> 6) & 7;
    int kcI  = idx >> 9;
    int n = nt * 8 + (lane >> 2);
    int k = kcI * 16 + r * 8 + (lane & 3) * 2;

    float f0 = W[n * IND + k];
    float f1 = W[n * IND + k + 1];
    uint32_t u0 = __float_as_uint(f0), u1 = __float_as_uint(f1);
    g_WfragHi[idx] = __byte_perm(u0, u1, 0x7632);   // truncated-bf16 pair (exact split)
    float l0 = f0 - __uint_as_float(u0 & 0xFFFF0000u);
    float l1 = f1 - __uint_as_float(u1 & 0xFFFF0000u);
    uint32_t lo;
    asm("cvt.rn.bf16x2.f32 %0, %1, %2;" : "=r"(lo) : "f"(l1), "f"(l0));
    g_WfragLo[idx] = lo;
}

// ---------------------------------------------------------------------------
// Kernel 1: pre0 = x @ W_ih0^T + b_ih0 + b_hh0  via split-bf16 mma.sync.
// M = 65536, N = 64, K = 768. CTA = 128 rows, 4 warps x 32 rows.
// ---------------------------------------------------------------------------
__device__ __forceinline__ void split2(float2 f, uint32_t& hi, uint32_t& lo) {
    uint32_t u0 = __float_as_uint(f.x), u1 = __float_as_uint(f.y);
    hi = __byte_perm(u0, u1, 0x7632);
    float l0 = f.x - __uint_as_float(u0 & 0xFFFF0000u);
    float l1 = f.y - __uint_as_float(u1 & 0xFFFF0000u);
    asm("cvt.rn.bf16x2.f32 %0, %1, %2;" : "=r"(lo) : "f"(l1), "f"(l0));
}

#define MMA4(C, A, B0, B1)                                                      \
    asm volatile(                                                               \
        "mma.sync.aligned.m16n8k16.row.col.f32.bf16.bf16.f32 "                  \
        "{%0,%1,%2,%3}, {%4,%5,%6,%7}, {%8,%9}, {%0,%1,%2,%3};"                 \
        : "+f"((C)[0]), "+f"((C)[1]), "+f"((C)[2]), "+f"((C)[3])                \
        : "r"((A)[0]), "r"((A)[1]), "r"((A)[2]), "r"((A)[3]),                   \
          "r"(B0), "r"(B1))

__global__ __launch_bounds__(128) void input_gemm_kernel(
    const float* __restrict__ x,
    const float* __restrict__ bih, const float* __restrict__ bhh)
{
    int tid  = threadIdx.x;
    int warp = tid >> 5, lane = tid & 31;
    int g = lane >> 2, tg = lane & 3;
    int base = blockIdx.x * 128 + warp * 32;
    const float* xr0 = x + (size_t)(base + g)      * IND + tg * 2;
    const float* xr1 = x + (size_t)(base + g + 8)  * IND + tg * 2;
    const float* xr2 = x + (size_t)(base + g + 16) * IND + tg * 2;
    const float* xr3 = x + (size_t)(base + g + 24) * IND + tg * 2;

    float c0[8][4], c1[8][4];
#pragma unroll
    for (int nt = 0; nt < 8; nt++)
#pragma unroll
        for (int i = 0; i < 4; i++) { c0[nt][i] = 0.f; c1[nt][i] = 0.f; }

    const uint2* fragHi = (const uint2*)g_WfragHi;
    const uint2* fragLo = (const uint2*)g_WfragLo;

    for (int kcI = 0; kcI < NKC; kcI++) {
        int kc = kcI * 16;
        uint32_t ah0[4], al0[4], ah1[4], al1[4];
        split2(*(const float2*)(xr0 + kc),     ah0[0], al0[0]);
        split2(*(const float2*)(xr1 + kc),     ah0[1], al0[1]);
        split2(*(const float2*)(xr0 + kc + 8), ah0[2], al0[2]);
        split2(*(const float2*)(xr1 + kc + 8), ah0[3], al0[3]);
        split2(*(const float2*)(xr2 + kc),     ah1[0], al1[0]);
        split2(*(const float2*)(xr3 + kc),     ah1[1], al1[1]);
        split2(*(const float2*)(xr2 + kc + 8), ah1[2], al1[2]);
        split2(*(const float2*)(xr3 + kc + 8), ah1[3], al1[3]);
#pragma unroll
        for (int nt = 0; nt < 8; nt++) {
            int fidx = (kcI * 8 + nt) * 32 + lane;
            uint2 bh = fragHi[fidx];      // coalesced 256B/warp
            uint2 bl = fragLo[fidx];
            MMA4(c0[nt], ah0, bh.x, bh.y);
            MMA4(c1[nt], ah1, bh.x, bh.y);
            MMA4(c0[nt], al0, bh.x, bh.y);
            MMA4(c1[nt], al1, bh.x, bh.y);
            MMA4(c0[nt], ah0, bl.x, bl.y);
            MMA4(c1[nt], ah1, bl.x, bl.y);
        }
    }

#pragma unroll
    for (int nt = 0; nt < 8; nt++) {
        int n0 = nt * 8 + tg * 2;
        float bb0 = bih[n0]     + bhh[n0];
        float bb1 = bih[n0 + 1] + bhh[n0 + 1];
        *(float2*)(g_pre0 + (size_t)(base + g)      * HID + n0) = make_float2(c0[nt][0] + bb0, c0[nt][1] + bb1);
        *(float2*)(g_pre0 + (size_t)(base + g + 8)  * HID + n0) = make_float2(c0[nt][2] + bb0, c0[nt][3] + bb1);
        *(float2*)(g_pre0 + (size_t)(base + g + 16) * HID + n0) = make_float2(c1[nt][0] + bb0, c1[nt][1] + bb1);
        *(float2*)(g_pre0 + (size_t)(base + g + 24) * HID + n0) = make_float2(c1[nt][2] + bb0, c1[nt][3] + bb1);
    }
}

// ---------------------------------------------------------------------------
// Kernel 2: fused 3-layer recurrence. 192 threads = 6 warps, 2 warps/layer,
// ONE thread per output neuron (no shfl reduction, no duplicated compute).
// Weight rows register-resident as f32x2; h vectors in smem, broadcast reads.
// ---------------------------------------------------------------------------
typedef unsigned long long ull;

__device__ __forceinline__ ull fma2(ull a, ull b, ull c) {
    ull d; asm("fma.rn.f32x2 %0, %1, %2, %3;" : "=l"(d) : "l"(a), "l"(b), "l"(c)); return d;
}
__device__ __forceinline__ ull add2(ull a, ull b) {
    ull d; asm("add.rn.f32x2 %0, %1, %2;" : "=l"(d) : "l"(a), "l"(b)); return d;
}
__device__ __forceinline__ float red2(ull v) {
    float lo, hi; asm("mov.b64 {%0,%1}, %2;" : "=f"(lo), "=f"(hi) : "l"(v)); return lo + hi;
}
__device__ __forceinline__ ull packf2(float a, float b) {
    ull d; asm("mov.b64 %0, {%1,%2};" : "=l"(d) : "f"(a), "f"(b)); return d;
}

// tanh via ex2.approx + rcp.approx; |err| ~1e-6 (validated: rel_err 1.04e-5).
__device__ __forceinline__ float fast_tanh(float x) {
    x = fminf(fmaxf(x, -15.0f), 15.0f);
    float e;
    asm("{ .reg .f32 t;\n\t"
        "  mul.f32 t, %1, 0f4038AA3B;\n\t"          // 2*log2(e)
        "  ex2.approx.f32 %0, t; }"
        : "=f"(e) : "f"(x));
    float r;
    asm("rcp.approx.f32 %0, %1;" : "=f"(r) : "f"(e + 1.0f));
    return (e - 1.0f) * r;
}

// 64-wide dot: 32 fma2 into 4 accumulators, operands via 16 broadcast LDS.128.
__device__ __forceinline__ void dot64acc(const ull* w, const float* h,
                                         ull& a0, ull& a1, ull& a2, ull& a3) {
    const ulonglong2* hp = (const ulonglong2*)h;
#pragma unroll
    for (int i = 0; i < 8; i++) {
        ulonglong2 u = hp[2*i];
        ulonglong2 v = hp[2*i + 1];
        a0 = fma2(w[4*i],     u.x, a0);
        a1 = fma2(w[4*i + 1], u.y, a1);
        a2 = fma2(w[4*i + 2], v.x, a2);
        a3 = fma2(w[4*i + 3], v.y, a3);
    }
}

#define BARALL() asm volatile("bar.sync 0, 192;" ::: "memory")

__global__ __launch_bounds__(192, 1) void rnn_kernel(
    const float* __restrict__ Whh0,
    const float* __restrict__ Wih1, const float* __restrict__ Whh1,
    const float* __restrict__ bih1, const float* __restrict__ bhh1,
    const float* __restrict__ Wih2, const float* __restrict__ Whh2,
    const float* __restrict__ bih2, const float* __restrict__ bhh2,
    const float* __restrict__ fcw,  const float* __restrict__ fcb,
    float* __restrict__ out)
{
    __shared__ __align__(16) float hs[3][2][HID];   // [layer][slot][neuron]

    int tid  = threadIdx.x;
    int w    = tid >> 5;           // warp 0..5
    int lane = tid & 31;
    int layer = w >> 1;            // 0,0,1,1,2,2
    int j = (w & 1) * 32 + lane;   // neuron owned by this thread
    int b = blockIdx.x;

    for (int i = tid; i < 3 * 2 * HID; i += 192) (&hs[0][0][0])[i] = 0.f;

    // Register-resident weight rows (f32x2-packed).
    ull wa[32], wb[32];
    float bias = 0.f;
#define LOADROW(dst, src) do {                                                  \
        const float4* p4 = (const float4*)((src) + j * HID);                    \
        _Pragma("unroll")                                                       \
        for (int i = 0; i < 16; i++) {                                          \
            float4 v = p4[i];                                                   \
            (dst)[2*i]     = packf2(v.x, v.y);                                  \
            (dst)[2*i + 1] = packf2(v.z, v.w);                                  \
        }                                                                       \
    } while (0)

    const float* prePtr = g_pre0 + (size_t)b * SEQ * HID + j;
    float pre_cur = 0.f;

    if (layer == 0) {
        LOADROW(wa, Whh0);
        pre_cur = __ldg(prePtr);
        prePtr += HID;
    } else if (layer == 1) {
        LOADROW(wa, Wih1); LOADROW(wb, Whh1); bias = bih1[j] + bhh1[j];
    } else {
        LOADROW(wa, Wih2); LOADROW(wb, Whh2); bias = bih2[j] + bhh2[j];
    }
    __syncthreads();

    // STEP0(P): layer0 time t (parity P): reads own h0 slot P^1, writes slot P.
#define STEP0(P) do {                                                           \
        float pre_next = __ldg(prePtr); prePtr += HID;                          \
        ull a0 = 0, a1 = 0, a2 = 0, a3 = 0;                                     \
        dot64acc(wa, &hs[0][(P)^1][0], a0, a1, a2, a3);                         \
        float d = red2(add2(add2(a0, a1), add2(a2, a3)));                       \
        hs[0][P][j] = fast_tanh(pre_cur + d);                                   \
        pre_cur = pre_next;                                                     \
    } while (0)

    // STEPL(P, LI): layer LI (1 or 2) time t (parity P): reads h_{LI-1} slot P
    // and own h_LI slot P^1, writes own slot P.
#define STEPL(P, LI) do {                                                       \
        ull a0 = 0, a1 = 0, a2 = 0, a3 = 0;                                     \
        dot64acc(wa, &hs[(LI)-1][P][0],   a0, a1, a2, a3);                      \
        dot64acc(wb, &hs[LI][(P)^1][0],   a0, a1, a2, a3);                      \
        float d = red2(add2(add2(a0, a1), add2(a2, a3)));                       \
        hs[LI][P][j] = fast_tanh(bias + d);                                     \
    } while (0)

    // Pipeline step s = 0..513: layer0 runs t=s, layer1 t=s-1, layer2 t=s-2.
    // Each warp executes exactly 514 BARALLs.
    if (layer == 0) {
        STEP0(0); BARALL();                       // s=0   (t=0)
        STEP0(1); BARALL();                       // s=1   (t=1)
#pragma unroll 1
        for (int it = 0; it < 255; it++) {        // s=2..511 (t=2..511)
            STEP0(0); BARALL();
            STEP0(1); BARALL();
        }
        BARALL();                                 // s=512
        BARALL();                                 // s=513
    } else if (layer == 1) {
        BARALL();                                 // s=0
        STEPL(0, 1); BARALL();                    // s=1   (t=0)
#pragma unroll 1
        for (int it = 0; it < 255; it++) {        // s=2..511 (t=1..510)
            STEPL(1, 1); BARALL();
            STEPL(0, 1); BARALL();
        }
        STEPL(1, 1); BARALL();                    // s=512 (t=511)
        BARALL();                                 // s=513
    } else {
        BARALL();                                 // s=0
        BARALL();                                 // s=1
#pragma unroll 1
        for (int it = 0; it < 255; it++) {        // s=2..511 (t=0..509)
            STEPL(0, 2); BARALL();
            STEPL(1, 2); BARALL();
        }
        STEPL(0, 2); BARALL();                    // s=512 (t=510)
        STEPL(1, 2); BARALL();                    // s=513 (t=511)
    }

    // h2[511] is in slot 1 (t=511 parity 1); last BARALL made it visible.
    if (tid < 32) {
        float sacc = fcw[lane] * hs[2][1][lane] + fcw[lane + 32] * hs[2][1][lane + 32];
#pragma unroll
        for (int o = 16; o; o >>= 1) sacc += __shfl_xor_sync(0xFFFFFFFFu, sacc, o);
        if (lane == 0) out[b] = sacc + fcb[0];
    }
}

// ---------------------------------------------------------------------------
// Launch. Input order: x, fixation_num, W_ih0, W_hh0, b_ih0, b_hh0, W_ih1,
// W_hh1, b_ih1, b_hh1, W_ih2, W_hh2, b_ih2, b_hh2, fc_w, fc_b
// ---------------------------------------------------------------------------
extern "C" void kernel_launch(void* const* d_in, const int* in_sizes, int n_in,
                              void* d_out, int out_size)
{
    const float* x    = (const float*)d_in[0];
    const float* Wih0 = (const float*)d_in[2];
    const float* Whh0 = (const float*)d_in[3];
    const float* bih0 = (const float*)d_in[4];
    const float* bhh0 = (const float*)d_in[5];
    const float* Wih1 = (const float*)d_in[6];
    const float* Whh1 = (const float*)d_in[7];
    const float* bih1 = (const float*)d_in[8];
    const float* bhh1 = (const float*)d_in[9];
    const float* Wih2 = (const float*)d_in[10];
    const float* Whh2 = (const float*)d_in[11];
    const float* bih2 = (const float*)d_in[12];
    const float* bhh2 = (const float*)d_in[13];
    const float* fcw  = (const float*)d_in[14];
    const float* fcb  = (const float*)d_in[15];
    float* out = (float*)d_out;

    split_w_kernel<<<(NFRAG * 2 + 255) / 256, 256>>>(Wih0);
    input_gemm_kernel<<<(BATCH * SEQ) / 128, 128>>>(x, bih0, bhh0);
    rnn_kernel<<<BATCH, 192>>>(Whh0, Wih1, Whh1, bih1, bhh1,
                               Wih2, Whh2, bih2, bhh2, fcw, fcb, out);
}

// round 6
// speedup vs baseline: 1.1004x; 1.1004x over previous
#include <cuda_runtime.h>
#include <cuda_bf16.h>
#include <cstdint>
#include <cstddef>

#define BATCH 128
#define SEQ   512
#define IND   768
#define HID   64
#define NKC   (IND / 16)       // 48 k-chunks
#define NFRAG (NKC * 8 * 32)   // fragment count * lanes

// Scratch (allocation-free rule: __device__ globals). +HID pad: the recurrence
// prefetches pre[t+1] unconditionally, including t=511 of the last batch.
__device__ float    g_pre0[BATCH * SEQ * HID + HID];
__device__ uint32_t g_WfragHi[NFRAG * 2];        // W_ih0 hi bf16, mma-B packed
__device__ uint32_t g_WfragLo[NFRAG * 2];        // W_ih0 lo bf16, mma-B packed

// Dummy kernel: shifts the ncu -s 5 profiled slot onto rnn_kernel.
__global__ void probe_kernel() {}

// ---------------------------------------------------------------------------
// Kernel 0: split W_ih0 into bf16 hi/lo AND pack into mma B-fragment layout.
// ---------------------------------------------------------------------------
__global__ void split_w_kernel(const float* __restrict__ W) {
    int idx = blockIdx.x * 256 + threadIdx.x;       // 0 .. NFRAG*2-1
    if (idx >= NFRAG * 2) return;
    int r    = idx & 1;
    int lane = (idx >> 1) & 31;
    int nt   = (idx >> 6) & 7;
    int kcI  = idx >> 9;
    int n = nt * 8 + (lane >> 2);
    int k = kcI * 16 + r * 8 + (lane & 3) * 2;

    float f0 = W[n * IND + k];
    float f1 = W[n * IND + k + 1];
    uint32_t u0 = __float_as_uint(f0), u1 = __float_as_uint(f1);
    g_WfragHi[idx] = __byte_perm(u0, u1, 0x7632);   // truncated-bf16 pair (exact split)
    float l0 = f0 - __uint_as_float(u0 & 0xFFFF0000u);
    float l1 = f1 - __uint_as_float(u1 & 0xFFFF0000u);
    uint32_t lo;
    asm("cvt.rn.bf16x2.f32 %0, %1, %2;" : "=r"(lo) : "f"(l1), "f"(l0));
    g_WfragLo[idx] = lo;
}

// ---------------------------------------------------------------------------
// Kernel 1: pre0 = x @ W_ih0^T + b_ih0 + b_hh0  via split-bf16 mma.sync.
// M = 65536, N = 64, K = 768. CTA = 128 rows, 4 warps x 32 rows.
// ---------------------------------------------------------------------------
__device__ __forceinline__ void split2(float2 f, uint32_t& hi, uint32_t& lo) {
    uint32_t u0 = __float_as_uint(f.x), u1 = __float_as_uint(f.y);
    hi = __byte_perm(u0, u1, 0x7632);
    float l0 = f.x - __uint_as_float(u0 & 0xFFFF0000u);
    float l1 = f.y - __uint_as_float(u1 & 0xFFFF0000u);
    asm("cvt.rn.bf16x2.f32 %0, %1, %2;" : "=r"(lo) : "f"(l1), "f"(l0));
}

#define MMA4(C, A, B0, B1)                                                      \
    asm volatile(                                                               \
        "mma.sync.aligned.m16n8k16.row.col.f32.bf16.bf16.f32 "                  \
        "{%0,%1,%2,%3}, {%4,%5,%6,%7}, {%8,%9}, {%0,%1,%2,%3};"                 \
        : "+f"((C)[0]), "+f"((C)[1]), "+f"((C)[2]), "+f"((C)[3])                \
        : "r"((A)[0]), "r"((A)[1]), "r"((A)[2]), "r"((A)[3]),                   \
          "r"(B0), "r"(B1))

__global__ __launch_bounds__(128) void input_gemm_kernel(
    const float* __restrict__ x,
    const float* __restrict__ bih, const float* __restrict__ bhh)
{
    int tid  = threadIdx.x;
    int warp = tid >> 5, lane = tid & 31;
    int g = lane >> 2, tg = lane & 3;
    int base = blockIdx.x * 128 + warp * 32;
    const float* xr0 = x + (size_t)(base + g)      * IND + tg * 2;
    const float* xr1 = x + (size_t)(base + g + 8)  * IND + tg * 2;
    const float* xr2 = x + (size_t)(base + g + 16) * IND + tg * 2;
    const float* xr3 = x + (size_t)(base + g + 24) * IND + tg * 2;

    float c0[8][4], c1[8][4];
#pragma unroll
    for (int nt = 0; nt < 8; nt++)
#pragma unroll
        for (int i = 0; i < 4; i++) { c0[nt][i] = 0.f; c1[nt][i] = 0.f; }

    const uint2* fragHi = (const uint2*)g_WfragHi;
    const uint2* fragLo = (const uint2*)g_WfragLo;

    for (int kcI = 0; kcI < NKC; kcI++) {
        int kc = kcI * 16;
        uint32_t ah0[4], al0[4], ah1[4], al1[4];
        split2(*(const float2*)(xr0 + kc),     ah0[0], al0[0]);
        split2(*(const float2*)(xr1 + kc),     ah0[1], al0[1]);
        split2(*(const float2*)(xr0 + kc + 8), ah0[2], al0[2]);
        split2(*(const float2*)(xr1 + kc + 8), ah0[3], al0[3]);
        split2(*(const float2*)(xr2 + kc),     ah1[0], al1[0]);
        split2(*(const float2*)(xr3 + kc),     ah1[1], al1[1]);
        split2(*(const float2*)(xr2 + kc + 8), ah1[2], al1[2]);
        split2(*(const float2*)(xr3 + kc + 8), ah1[3], al1[3]);
#pragma unroll
        for (int nt = 0; nt < 8; nt++) {
            int fidx = (kcI * 8 + nt) * 32 + lane;
            uint2 bh = fragHi[fidx];      // coalesced 256B/warp
            uint2 bl = fragLo[fidx];
            MMA4(c0[nt], ah0, bh.x, bh.y);
            MMA4(c1[nt], ah1, bh.x, bh.y);
            MMA4(c0[nt], al0, bh.x, bh.y);
            MMA4(c1[nt], al1, bh.x, bh.y);
            MMA4(c0[nt], ah0, bl.x, bl.y);
            MMA4(c1[nt], ah1, bl.x, bl.y);
        }
    }

#pragma unroll
    for (int nt = 0; nt < 8; nt++) {
        int n0 = nt * 8 + tg * 2;
        float bb0 = bih[n0]     + bhh[n0];
        float bb1 = bih[n0 + 1] + bhh[n0 + 1];
        *(float2*)(g_pre0 + (size_t)(base + g)      * HID + n0) = make_float2(c0[nt][0] + bb0, c0[nt][1] + bb1);
        *(float2*)(g_pre0 + (size_t)(base + g + 8)  * HID + n0) = make_float2(c0[nt][2] + bb0, c0[nt][3] + bb1);
        *(float2*)(g_pre0 + (size_t)(base + g + 16) * HID + n0) = make_float2(c1[nt][0] + bb0, c1[nt][1] + bb1);
        *(float2*)(g_pre0 + (size_t)(base + g + 24) * HID + n0) = make_float2(c1[nt][2] + bb0, c1[nt][3] + bb1);
    }
}

// ---------------------------------------------------------------------------
// Kernel 2: fused 3-layer recurrence, 384 threads (R4 mapping: 2 thr/neuron),
// DECOUPLED warpgroups via named-barrier producer/consumer rings:
//   b1/b2 = h0 ready (even/odd slot)   wg0 arrive -> wg1 sync
//   b3/b4 = h0 free                    wg1 arrive -> wg0 sync
//   b5/b6 = h1 ready                   wg1 arrive -> wg2 sync
//   b7/b8 = h1 free                    wg2 arrive -> wg1 sync
// Each blocking sync doubles as the wg-internal rendezvous (own-buffer
// visibility). Free-barriers are pre-armed once (2 slots of slack).
// ---------------------------------------------------------------------------
typedef unsigned long long ull;

__device__ __forceinline__ ull fma2(ull a, ull b, ull c) {
    ull d; asm("fma.rn.f32x2 %0, %1, %2, %3;" : "=l"(d) : "l"(a), "l"(b), "l"(c)); return d;
}
__device__ __forceinline__ ull add2(ull a, ull b) {
    ull d; asm("add.rn.f32x2 %0, %1, %2;" : "=l"(d) : "l"(a), "l"(b)); return d;
}
__device__ __forceinline__ float red2(ull v) {
    float lo, hi; asm("mov.b64 {%0,%1}, %2;" : "=f"(lo), "=f"(hi) : "l"(v)); return lo + hi;
}
__device__ __forceinline__ ull packf2(float a, float b) {
    ull d; asm("mov.b64 %0, {%1,%2};" : "=l"(d) : "f"(a), "f"(b)); return d;
}

// tanh via ex2.approx + rcp.approx; |err| ~1e-6 (validated: rel_err 1.04e-5).
__device__ __forceinline__ float fast_tanh(float x) {
    x = fminf(fmaxf(x, -15.0f), 15.0f);
    float e;
    asm("{ .reg .f32 t;\n\t"
        "  mul.f32 t, %1, 0f4038AA3B;\n\t"          // 2*log2(e)
        "  ex2.approx.f32 %0, t; }"
        : "=f"(e) : "f"(x));
    float r;
    asm("rcp.approx.f32 %0, %1;" : "=f"(r) : "f"(e + 1.0f));
    return (e - 1.0f) * r;
}

__device__ __forceinline__ void dot32acc(const ull* w, const float* hbase,
                                         ull& a0, ull& a1, ull& a2, ull& a3) {
    const ulonglong2* hp = (const ulonglong2*)hbase;   // 16B aligned (144B stride)
#pragma unroll
    for (int i = 0; i < 8; i += 2) {
        ulonglong2 u = hp[i];
        a0 = fma2(w[2*i],     u.x, a0);
        a1 = fma2(w[2*i + 1], u.y, a1);
        ulonglong2 v = hp[i + 1];
        a2 = fma2(w[2*i + 2], v.x, a2);
        a3 = fma2(w[2*i + 3], v.y, a3);
    }
}

#define BSYNC(id) asm volatile("bar.sync "   #id ", 256;" ::: "memory")
#define BARV(id)  asm volatile("bar.arrive " #id ", 256;" ::: "memory")

__global__ __launch_bounds__(384, 1) void rnn_kernel(
    const float* __restrict__ Whh0,
    const float* __restrict__ Wih1, const float* __restrict__ Whh1,
    const float* __restrict__ bih1, const float* __restrict__ bhh1,
    const float* __restrict__ Wih2, const float* __restrict__ Whh2,
    const float* __restrict__ bih2, const float* __restrict__ bhh2,
    const float* __restrict__ fcw,  const float* __restrict__ fcb,
    float* __restrict__ out)
{
    // hs[layer][slot][half][36]: +36 keeps the two 16-lane broadcast groups in
    // disjoint banks; every half-start is 16B aligned (144B stride).
    __shared__ __align__(16) float hs[3][2][2][36];

    int tid = threadIdx.x;
    int wg  = tid >> 7;            // warpgroup = layer (0,1,2)
    int wt  = tid & 127;
    int j = wt >> 1, half = wt & 1;
    int jh = j >> 5, jl = j & 31;
    int b = blockIdx.x;

    for (int i = tid; i < 3 * 2 * 2 * 36; i += 384) (&hs[0][0][0][0])[i] = 0.f;

    ull wa[16], wb[16];
    float bias = 0.f;
#define LOADW(dst, src) do {                                                    \
        const float4* p4 = (const float4*)((src) + j * HID + half * 32);        \
        _Pragma("unroll")                                                       \
        for (int i = 0; i < 8; i++) {                                           \
            float4 v = p4[i];                                                   \
            (dst)[2*i]     = packf2(v.x, v.y);                                  \
            (dst)[2*i + 1] = packf2(v.z, v.w);                                  \
        }                                                                       \
    } while (0)

    const float* prePtr = g_pre0 + (size_t)b * SEQ * HID + j;
    float pre_cur = 0.f;

    if (wg == 0) {
        LOADW(wa, Whh0);
        pre_cur = __ldg(prePtr);
        prePtr += HID;
    } else if (wg == 1) {
        LOADW(wa, Wih1); LOADW(wb, Whh1); bias = bih1[j] + bhh1[j];
    } else {
        LOADW(wa, Wih2); LOADW(wb, Whh2); bias = bih2[j] + bhh2[j];
    }
    __syncthreads();   // zeroed buffers + weights visible; barriers start clean

    if (wg == 0) {
        // -------- layer 0: produce h0[t] --------
#define W0STEP(P, FREEID, READYID) do {                                         \
        BSYNC(FREEID);            /* slot P free + wg0 rendezvous */            \
        float pre_next = __ldg(prePtr); prePtr += HID;                          \
        ull a0 = 0, a1 = 0, a2 = 0, a3 = 0;                                     \
        dot32acc(wa, &hs[0][(P)^1][half][0], a0, a1, a2, a3);                   \
        float d = red2(add2(add2(a0, a1), add2(a2, a3)));                       \
        d += __shfl_xor_sync(0xFFFFFFFFu, d, 1);                                \
        hs[0][P][jh][jl] = fast_tanh(pre_cur + d);                              \
        pre_cur = pre_next;                                                     \
        BARV(READYID);            /* h0[t] ready */                             \
    } while (0)
#pragma unroll 1
        for (int it = 0; it < 256; it++) {   // t = 2*it, 2*it+1
            W0STEP(0, 3, 1);
            W0STEP(1, 4, 2);
        }
    } else if (wg == 1) {
        BARV(3); BARV(4);         // pre-arm h0-free (2 slots of slack)
        // -------- layer 1: consume h0[t], produce h1[t] --------
#define W1STEP(P, RDY0, FREE0, FREE1, RDY1) do {                                \
        BSYNC(RDY0);              /* h0[t] ready + wg1 rendezvous */            \
        ull a0=0,a1=0,a2=0,a3=0, c0=0,c1=0,c2=0,c3=0;                           \
        dot32acc(wa, &hs[0][P][half][0],     a0, a1, a2, a3);                   \
        dot32acc(wb, &hs[1][(P)^1][half][0], c0, c1, c2, c3);                   \
        BARV(FREE0);              /* h0 slot P consumed */                      \
        float d = red2(add2(add2(add2(a0,c0), add2(a1,c1)),                     \
                            add2(add2(a2,c2), add2(a3,c3))));                   \
        d += __shfl_xor_sync(0xFFFFFFFFu, d, 1);                                \
        float hv = fast_tanh(bias + d);                                         \
        BSYNC(FREE1);             /* h1 slot P free (wg2 consumed t-2) */       \
        hs[1][P][jh][jl] = hv;                                                  \
        BARV(RDY1);               /* h1[t] ready */                             \
    } while (0)
#pragma unroll 1
        for (int it = 0; it < 256; it++) {
            W1STEP(0, 1, 3, 7, 5);
            W1STEP(1, 2, 4, 8, 6);
        }
    } else {
        BARV(7); BARV(8);         // pre-arm h1-free
        // -------- layer 2: consume h1[t], produce h2[t] --------
#define W2STEP(P, RDY1, FREE1) do {                                             \
        BSYNC(RDY1);              /* h1[t] ready + wg2 rendezvous */            \
        ull a0=0,a1=0,a2=0,a3=0, c0=0,c1=0,c2=0,c3=0;                           \
        dot32acc(wa, &hs[1][P][half][0],     a0, a1, a2, a3);                   \
        dot32acc(wb, &hs[2][(P)^1][half][0], c0, c1, c2, c3);                   \
        BARV(FREE1);              /* h1 slot P consumed */                      \
        float d = red2(add2(add2(add2(a0,c0), add2(a1,c1)),                     \
                            add2(add2(a2,c2), add2(a3,c3))));                   \
        d += __shfl_xor_sync(0xFFFFFFFFu, d, 1);                                \
        hs[2][P][jh][jl] = fast_tanh(bias + d);                                 \
    } while (0)
#pragma unroll 1
        for (int it = 0; it < 256; it++) {
            W2STEP(0, 5, 7);
            W2STEP(1, 6, 8);
        }
    }

    __syncthreads();   // h2[511] (slot 1) visible to all

    if (tid < 32) {
        float sacc = fcw[tid] * hs[2][1][0][tid] + fcw[tid + 32] * hs[2][1][1][tid];
#pragma unroll
        for (int o = 16; o; o >>= 1) sacc += __shfl_xor_sync(0xFFFFFFFFu, sacc, o);
        if (tid == 0) out[b] = sacc + fcb[0];
    }
}

// ---------------------------------------------------------------------------
// Launch. Input order: x, fixation_num, W_ih0, W_hh0, b_ih0, b_hh0, W_ih1,
// W_hh1, b_ih1, b_hh1, W_ih2, W_hh2, b_ih2, b_hh2, fc_w, fc_b
// ---------------------------------------------------------------------------
extern "C" void kernel_launch(void* const* d_in, const int* in_sizes, int n_in,
                              void* d_out, int out_size)
{
    const float* x    = (const float*)d_in[0];
    const float* Wih0 = (const float*)d_in[2];
    const float* Whh0 = (const float*)d_in[3];
    const float* bih0 = (const float*)d_in[4];
    const float* bhh0 = (const float*)d_in[5];
    const float* Wih1 = (const float*)d_in[6];
    const float* Whh1 = (const float*)d_in[7];
    const float* bih1 = (const float*)d_in[8];
    const float* bhh1 = (const float*)d_in[9];
    const float* Wih2 = (const float*)d_in[10];
    const float* Whh2 = (const float*)d_in[11];
    const float* bih2 = (const float*)d_in[12];
    const float* bhh2 = (const float*)d_in[13];
    const float* fcw  = (const float*)d_in[14];
    const float* fcb  = (const float*)d_in[15];
    float* out = (float*)d_out;

    probe_kernel<<<1, 32>>>();   // shifts ncu -s 5 slot onto rnn_kernel
    split_w_kernel<<<(NFRAG * 2 + 255) / 256, 256>>>(Wih0);
    input_gemm_kernel<<<(BATCH * SEQ) / 128, 128>>>(x, bih0, bhh0);
    rnn_kernel<<<BATCH, 384>>>(Whh0, Wih1, Whh1, bih1, bhh1,
                               Wih2, Whh2, bih2, bhh2, fcw, fcb, out);
}